// round 11
// baseline (speedup 1.0000x reference)
#include <cuda_runtime.h>

#define NQ 4
#define DIM 16
typedef unsigned long long u64;

// Coefficient tensor published by leader block: [w][27 triples][4 slots],
// duplicated float pairs in u64 for fma.rn.f32x2. Plus handshake state.
__device__ u64 g_Tp[4 * 27 * 4];
__device__ int g_flag = 0;
__device__ int g_done = 0;

__device__ __forceinline__ u64 pk2(float lo, float hi) {
    u64 r; asm("mov.b64 %0, {%1,%2};" : "=l"(r) : "f"(lo), "f"(hi)); return r;
}
__device__ __forceinline__ void upk2(u64 v, float& lo, float& hi) {
    asm("mov.b64 {%0,%1}, %2;" : "=f"(lo), "=f"(hi) : "l"(v));
}
__device__ __forceinline__ u64 fma2(u64 a, u64 b, u64 c) {
    u64 d; asm("fma.rn.f32x2 %0, %1, %2, %3;" : "=l"(d) : "l"(a), "l"(b), "l"(c)); return d;
}

// ---------------------------------------------------------------------------
// Single kernel. Block 0 builds the multilinear coefficient tensors T_w
// (U-sim on identity columns -> M_w = Re(U^H D_w U) -> (1,cos,sin) transform),
// publishes them to g_Tp, and raises g_flag. Other blocks overlap their x
// loads + sincos with that latency, then spin briefly, copy T to shared, and
// evaluate:  out_w(b) = <T_w, u0 x u1 x u2 x u3>, u_q = (1, cos x_q, sin x_q).
// 4 elements/thread as 2 packed f32x2 pairs; h-split STG.64 stores.
// Flag/done-counter reset by the last finishing block (replay-deterministic).
// ---------------------------------------------------------------------------
template <bool GUARD>
__global__ __launch_bounds__(256, 3)
void qlayer_one(const float4* __restrict__ x4, float2* __restrict__ out2,
                const float* __restrict__ W, int n_layers, int B, int Q) {
    __shared__ float Ur[DIM][DIM + 1], Ui[DIM][DIM + 1]; // [idx][col]
    __shared__ float Msh[4][DIM][DIM];
    __shared__ __align__(16) u64 sT[4 * 27 * 4];

    const int t = threadIdx.x;
    const bool leader = (blockIdx.x == 0);

    if (leader) {
        // ---- Phase 1a: simulate circuit columns (threads 0..15) ----
        if (t < DIM) {
            const int col = t;
            float ar[DIM], ai[DIM];
#pragma unroll
            for (int i = 0; i < DIM; i++) { ar[i] = (i == col) ? 1.f : 0.f; ai[i] = 0.f; }

            for (int l = 0; l < n_layers; l++) {
#pragma unroll
                for (int w = 0; w < NQ; w++) {
                    const float* wp = &W[(l * NQ + w) * 3];
                    float sx, cx, sy, cy, sz, cz;
                    __sincosf(0.5f * wp[0], &sx, &cx);
                    __sincosf(0.5f * wp[1], &sy, &cy);
                    __sincosf(0.5f * wp[2], &sz, &cz);
                    const int mask = 1 << (NQ - 1 - w);
#pragma unroll
                    for (int pi = 0; pi < DIM / 2; pi++) {
                        const int low = pi & (mask - 1);
                        const int i0 = ((pi - low) << 1) | low;
                        const int i1 = i0 | mask;
                        float a0r, a0i, a1r, a1i;
                        // RX
                        a0r = ar[i0]; a0i = ai[i0]; a1r = ar[i1]; a1i = ai[i1];
                        ar[i0] = cx * a0r + sx * a1i;  ai[i0] = cx * a0i - sx * a1r;
                        ar[i1] = sx * a0i + cx * a1r;  ai[i1] = -sx * a0r + cx * a1i;
                        // RY
                        a0r = ar[i0]; a0i = ai[i0]; a1r = ar[i1]; a1i = ai[i1];
                        ar[i0] = cy * a0r - sy * a1r;  ai[i0] = cy * a0i - sy * a1i;
                        ar[i1] = sy * a0r + cy * a1r;  ai[i1] = sy * a0i + cy * a1i;
                        // RZ
                        a0r = ar[i0]; a0i = ai[i0]; a1r = ar[i1]; a1i = ai[i1];
                        ar[i0] = cz * a0r + sz * a0i;  ai[i0] = cz * a0i - sz * a0r;
                        ar[i1] = cz * a1r - sz * a1i;  ai[i1] = cz * a1i + sz * a1r;
                    }
                }
                // CNOT ring: new[idx] = old[perm[idx]]
#pragma unroll
                for (int w = 0; w < NQ; w++) {
                    const int tq = (w + 1) & (NQ - 1);
                    float nr[DIM], ni[DIM];
#pragma unroll
                    for (int idx = 0; idx < DIM; idx++) {
                        const int src = ((idx >> (NQ - 1 - w)) & 1) ? (idx ^ (1 << (NQ - 1 - tq))) : idx;
                        nr[idx] = ar[src]; ni[idx] = ai[src];
                    }
#pragma unroll
                    for (int idx = 0; idx < DIM; idx++) { ar[idx] = nr[idx]; ai[idx] = ni[idx]; }
                }
            }
#pragma unroll
            for (int i = 0; i < DIM; i++) { Ur[i][t] = ar[i]; Ui[i][t] = ai[i]; }
        }
        __syncthreads();

        // ---- Phase 1b: M_w[i][j] = sum_idx z_w(idx)(Ur_i Ur_j + Ui_i Ui_j) ----
        for (int e = t; e < 4 * DIM * DIM; e += 256) {
            const int w = e >> 8, i = (e >> 4) & 15, j = e & 15;
            float acc = 0.f;
#pragma unroll
            for (int idx = 0; idx < DIM; idx++) {
                const float z = ((idx >> (NQ - 1 - w)) & 1) ? -1.f : 1.f;
                acc += z * (Ur[idx][i] * Ur[idx][j] + Ui[idx][i] * Ui[idx][j]);
            }
            Msh[w][i][j] = acc;
        }
        __syncthreads();

        // ---- Phase 1c: T_w via per-qubit (1,cos,sin) transform ----
        for (int e = t; e < 4 * 81; e += 256) {
            const int w = e / 81, r = e % 81;
            const int tq4[4] = { r / 27, (r / 9) % 3, (r / 3) % 3, r % 3 };
            const int   P[3][2]  = { {0, 3}, {0, 3}, {1, 2} };
            const float Cf[3][2] = { {0.5f, 0.5f}, {0.5f, -0.5f}, {0.5f, 0.5f} };
            float acc = 0.f;
            for (int a = 0; a < 2; a++)
            for (int b = 0; b < 2; b++)
            for (int c = 0; c < 2; c++)
            for (int d = 0; d < 2; d++) {
                const int p0 = P[tq4[0]][a], p1 = P[tq4[1]][b], p2 = P[tq4[2]][c], p3 = P[tq4[3]][d];
                const float co = Cf[tq4[0]][a] * Cf[tq4[1]][b] * Cf[tq4[2]][c] * Cf[tq4[3]][d];
                const int i = ((p0 >> 1) << 3) | ((p1 >> 1) << 2) | ((p2 >> 1) << 1) | (p3 >> 1);
                const int j = ((p0 & 1) << 3) | ((p1 & 1) << 2) | ((p2 & 1) << 1) | (p3 & 1);
                acc += co * Msh[w][i][j];
            }
            const u64 v = pk2(acc, acc);
            sT[(w * 27 + r / 3) * 4 + (r % 3)] = v;
            g_Tp[(w * 27 + r / 3) * 4 + (r % 3)] = v;
        }
        if (t < 4 * 27) { sT[t * 4 + 3] = 0ull; g_Tp[t * 4 + 3] = 0ull; }
        __threadfence();
        __syncthreads();
        if (t == 0) atomicExch(&g_flag, 1);
    }

    // ---- Front work (all blocks): x loads + sincos, independent of T ----
    const int tid = blockIdx.x * blockDim.x + t;
    const bool active = (tid < Q);

    u64 cA[4], sA[4], cB[4], sB[4];
    {
        const float4 z4 = make_float4(0.f, 0.f, 0.f, 0.f);
        const float4 x0 = (active && (!GUARD || tid < B))         ? x4[tid]         : z4;
        const float4 x1 = (active && (!GUARD || tid + Q < B))     ? x4[tid + Q]     : z4;
        const float4 x2 = (active && (!GUARD || tid + 2 * Q < B)) ? x4[tid + 2 * Q] : z4;
        const float4 x3 = (active && (!GUARD || tid + 3 * Q < B)) ? x4[tid + 3 * Q] : z4;
        const float* p0 = &x0.x; const float* p1 = &x1.x;
        const float* p2 = &x2.x; const float* p3 = &x3.x;
#pragma unroll
        for (int q = 0; q < 4; q++) {
            float s0, c0, s1, c1, s2, c2, s3, c3;
            __sincosf(p0[q], &s0, &c0);
            __sincosf(p1[q], &s1, &c1);
            __sincosf(p2[q], &s2, &c2);
            __sincosf(p3[q], &s3, &c3);
            cA[q] = pk2(c0, c1); sA[q] = pk2(s0, s1);
            cB[q] = pk2(c2, c3); sB[q] = pk2(s2, s3);
        }
    }

    // ---- Non-leader blocks: wait for T, then copy to shared ----
    if (!leader) {
        if (t == 0) {
            while (atomicAdd(&g_flag, 0) == 0) { __nanosleep(64); }
        }
        __syncthreads();
        __threadfence();  // acquire: order g_Tp reads after flag observation
        for (int i = t; i < 4 * 27 * 4; i += 256) sT[i] = g_Tp[i];
        __syncthreads();
    }

    // ---- Phase 2: evaluation ----
    if (active) {
#pragma unroll
        for (int h = 0; h < 2; h++) {           // output halves: w = 2h, 2h+1
            u64 outA[2], outB[2];
#pragma unroll
            for (int wi = 0; wi < 2; wi++) {
                const u64* Tw = &sT[(2 * h + wi) * 27 * 4];
                u64 r0A, r0B;
#pragma unroll
                for (int t0 = 0; t0 < 3; t0++) {
                    u64 r1A, r1B;
#pragma unroll
                    for (int t1 = 0; t1 < 3; t1++) {
                        u64 r2A, r2B;
#pragma unroll
                        for (int t2 = 0; t2 < 3; t2++) {
                            const int base = ((t0 * 3 + t1) * 3 + t2) * 4;
                            const ulonglong2 ta = *reinterpret_cast<const ulonglong2*>(&Tw[base]);
                            const u64 T2 = Tw[base + 2];
                            const u64 vA = fma2(sA[3], T2, fma2(cA[3], ta.y, ta.x));
                            const u64 vB = fma2(sB[3], T2, fma2(cB[3], ta.y, ta.x));
                            if (t2 == 0)      { r2A = vA;                   r2B = vB; }
                            else if (t2 == 1) { r2A = fma2(cA[2], vA, r2A); r2B = fma2(cB[2], vB, r2B); }
                            else              { r2A = fma2(sA[2], vA, r2A); r2B = fma2(sB[2], vB, r2B); }
                        }
                        if (t1 == 0)      { r1A = r2A;                   r1B = r2B; }
                        else if (t1 == 1) { r1A = fma2(cA[1], r2A, r1A); r1B = fma2(cB[1], r2B, r1B); }
                        else              { r1A = fma2(sA[1], r2A, r1A); r1B = fma2(sB[1], r2B, r1B); }
                    }
                    if (t0 == 0)      { r0A = r1A;                   r0B = r1B; }
                    else if (t0 == 1) { r0A = fma2(cA[0], r1A, r0A); r0B = fma2(cB[0], r1B, r0B); }
                    else              { r0A = fma2(sA[0], r1A, r0A); r0B = fma2(sB[0], r1B, r0B); }
                }
                outA[wi] = r0A; outB[wi] = r0B;
            }
            float a0l, a0h, a1l, a1h, b0l, b0h, b1l, b1h;
            upk2(outA[0], a0l, a0h); upk2(outA[1], a1l, a1h);
            upk2(outB[0], b0l, b0h); upk2(outB[1], b1l, b1h);
            if (!GUARD || tid < B)         out2[(tid)         * 2 + h] = make_float2(a0l, a1l);
            if (!GUARD || tid + Q < B)     out2[(tid + Q)     * 2 + h] = make_float2(a0h, a1h);
            if (!GUARD || tid + 2 * Q < B) out2[(tid + 2 * Q) * 2 + h] = make_float2(b0l, b1l);
            if (!GUARD || tid + 3 * Q < B) out2[(tid + 3 * Q) * 2 + h] = make_float2(b0h, b1h);
        }
    }

    // ---- Epoch reset: last finishing block clears handshake state ----
    __syncthreads();
    if (t == 0) {
        const int d = atomicAdd(&g_done, 1);
        if (d == (int)gridDim.x - 1) {
            g_done = 0;
            g_flag = 0;
            __threadfence();
        }
    }
}

extern "C" void kernel_launch(void* const* d_in, const int* in_sizes, int n_in,
                              void* d_out, int out_size) {
    const float* x = (const float*)d_in[0];
    const float* weights = (const float*)d_in[1];
    const int B = in_sizes[0] / 4;            // (B, 4) float32
    const int n_layers = in_sizes[1] / 12;    // (L, 4, 3) float32

    const int Q = (B + 3) / 4;                // threads (4 elements each)
    const int blocks = (Q + 255) / 256;
    if (4 * Q == B) {
        qlayer_one<false><<<blocks, 256>>>((const float4*)x, (float2*)d_out,
                                           weights, n_layers, B, Q);
    } else {
        qlayer_one<true><<<blocks, 256>>>((const float4*)x, (float2*)d_out,
                                          weights, n_layers, B, Q);
    }
}

// round 12
// speedup vs baseline: 1.6531x; 1.6531x over previous
#include <cuda_runtime.h>

#define NQ 4
#define DIM 16
typedef unsigned long long u64;

// Coefficient tensor: [w][27 triples][4 slots], duplicated float pairs in u64
// (lo==hi) so an LDS feeds fma.rn.f32x2 directly. Written by precompute_T.
__device__ u64 g_Tp[4 * 27 * 4];

__device__ __forceinline__ u64 pk2(float lo, float hi) {
    u64 r; asm("mov.b64 %0, {%1,%2};" : "=l"(r) : "f"(lo), "f"(hi)); return r;
}
__device__ __forceinline__ void upk2(u64 v, float& lo, float& hi) {
    asm("mov.b64 {%0,%1}, %2;" : "=f"(lo), "=f"(hi) : "l"(v));
}
__device__ __forceinline__ u64 fma2(u64 a, u64 b, u64 c) {
    u64 d; asm("fma.rn.f32x2 %0, %1, %2, %3;" : "=l"(d) : "l"(a), "l"(b), "l"(c)); return d;
}

// ---------------------------------------------------------------------------
// Precompute kernel: one block. Builds U (16x16 complex) from weights by
// simulating the circuit on identity columns, M_w = Re(U^H D_w U), then the
// multilinear coefficient tensors T_w (basis (1, cos, sin) per qubit).
// Triggers programmatic launch completion after publishing g_Tp.
// ---------------------------------------------------------------------------
__global__ void precompute_T(const float* __restrict__ W, int n_layers) {
    __shared__ float Ur[DIM][DIM + 1], Ui[DIM][DIM + 1]; // [idx][col]
    __shared__ float Msh[4][DIM][DIM];

    const int t = threadIdx.x;

    if (t < DIM) {
        const int col = t;
        float ar[DIM], ai[DIM];
#pragma unroll
        for (int i = 0; i < DIM; i++) { ar[i] = (i == col) ? 1.f : 0.f; ai[i] = 0.f; }

        for (int l = 0; l < n_layers; l++) {
#pragma unroll
            for (int w = 0; w < NQ; w++) {
                const float* wp = &W[(l * NQ + w) * 3];
                float sx, cx, sy, cy, sz, cz;
                __sincosf(0.5f * wp[0], &sx, &cx);
                __sincosf(0.5f * wp[1], &sy, &cy);
                __sincosf(0.5f * wp[2], &sz, &cz);
                const int mask = 1 << (NQ - 1 - w);
#pragma unroll
                for (int pi = 0; pi < DIM / 2; pi++) {
                    const int low = pi & (mask - 1);
                    const int i0 = ((pi - low) << 1) | low;
                    const int i1 = i0 | mask;
                    float a0r, a0i, a1r, a1i;
                    // RX
                    a0r = ar[i0]; a0i = ai[i0]; a1r = ar[i1]; a1i = ai[i1];
                    ar[i0] = cx * a0r + sx * a1i;  ai[i0] = cx * a0i - sx * a1r;
                    ar[i1] = sx * a0i + cx * a1r;  ai[i1] = -sx * a0r + cx * a1i;
                    // RY
                    a0r = ar[i0]; a0i = ai[i0]; a1r = ar[i1]; a1i = ai[i1];
                    ar[i0] = cy * a0r - sy * a1r;  ai[i0] = cy * a0i - sy * a1i;
                    ar[i1] = sy * a0r + cy * a1r;  ai[i1] = sy * a0i + cy * a1i;
                    // RZ
                    a0r = ar[i0]; a0i = ai[i0]; a1r = ar[i1]; a1i = ai[i1];
                    ar[i0] = cz * a0r + sz * a0i;  ai[i0] = cz * a0i - sz * a0r;
                    ar[i1] = cz * a1r - sz * a1i;  ai[i1] = cz * a1i + sz * a1r;
                }
            }
            // CNOT ring: new[idx] = old[perm[idx]]
#pragma unroll
            for (int w = 0; w < NQ; w++) {
                const int tq = (w + 1) & (NQ - 1);
                float nr[DIM], ni[DIM];
#pragma unroll
                for (int idx = 0; idx < DIM; idx++) {
                    const int src = ((idx >> (NQ - 1 - w)) & 1) ? (idx ^ (1 << (NQ - 1 - tq))) : idx;
                    nr[idx] = ar[src]; ni[idx] = ai[src];
                }
#pragma unroll
                for (int idx = 0; idx < DIM; idx++) { ar[idx] = nr[idx]; ai[idx] = ni[idx]; }
            }
        }
#pragma unroll
        for (int i = 0; i < DIM; i++) { Ur[i][col] = ar[i]; Ui[i][col] = ai[i]; }
    }
    __syncthreads();

    // M_w[i][j] = sum_idx z_w(idx) * (Ur[idx][i]Ur[idx][j] + Ui[idx][i]Ui[idx][j])
    for (int e = t; e < 4 * DIM * DIM; e += blockDim.x) {
        const int w = e >> 8, i = (e >> 4) & 15, j = e & 15;
        float acc = 0.f;
#pragma unroll
        for (int idx = 0; idx < DIM; idx++) {
            const float z = ((idx >> (NQ - 1 - w)) & 1) ? -1.f : 1.f;
            acc += z * (Ur[idx][i] * Ur[idx][j] + Ui[idx][i] * Ui[idx][j]);
        }
        Msh[w][i][j] = acc;
    }
    __syncthreads();

    // T_w[t0,t1,t2,t3] via the per-qubit (1,cos,sin) transform:
    //   t=0 (const): p=00 coef .5, p=11 coef .5
    //   t=1 (cos)  : p=00 coef .5, p=11 coef -.5
    //   t=2 (sin)  : p=01 coef .5, p=10 coef .5
    for (int e = t; e < 4 * 81; e += blockDim.x) {
        const int w = e / 81, r = e % 81;
        const int tq4[4] = { r / 27, (r / 9) % 3, (r / 3) % 3, r % 3 };
        const int   P[3][2]  = { {0, 3}, {0, 3}, {1, 2} };
        const float Cf[3][2] = { {0.5f, 0.5f}, {0.5f, -0.5f}, {0.5f, 0.5f} };
        float acc = 0.f;
        for (int a = 0; a < 2; a++)
        for (int b = 0; b < 2; b++)
        for (int c = 0; c < 2; c++)
        for (int d = 0; d < 2; d++) {
            const int p0 = P[tq4[0]][a], p1 = P[tq4[1]][b], p2 = P[tq4[2]][c], p3 = P[tq4[3]][d];
            const float co = Cf[tq4[0]][a] * Cf[tq4[1]][b] * Cf[tq4[2]][c] * Cf[tq4[3]][d];
            const int i = ((p0 >> 1) << 3) | ((p1 >> 1) << 2) | ((p2 >> 1) << 1) | (p3 >> 1);
            const int j = ((p0 & 1) << 3) | ((p1 & 1) << 2) | ((p2 & 1) << 1) | (p3 & 1);
            acc += co * Msh[w][i][j];
        }
        const unsigned ui = __float_as_uint(acc);
        g_Tp[(w * 27 + r / 3) * 4 + (r % 3)] = ((u64)ui << 32) | (u64)ui;
    }
    for (int e = t; e < 4 * 27; e += blockDim.x) g_Tp[e * 4 + 3] = 0ull;
    __threadfence();
    __syncthreads();
    cudaTriggerProgrammaticLaunchCompletion();
}

// ---------------------------------------------------------------------------
// Main kernel (PDL secondary): front work (x loads + sincos) runs BEFORE the
// grid dependency sync, overlapping the precompute kernel. Then T -> shared,
// then the proven R8 evaluation: 4 elements/thread as 2 packed f32x2 pairs,
// h-split STG.64 stores.  out_w(b) = <T_w, u0 x u1 x u2 x u3>.
// ---------------------------------------------------------------------------
template <bool GUARD>
__global__ __launch_bounds__(256, 4)
void qlayer_main(const float4* __restrict__ x4, float2* __restrict__ out2,
                 int B, int Q) {
    __shared__ __align__(16) u64 sT[4 * 27 * 4];

    const int tid = blockIdx.x * blockDim.x + threadIdx.x;
    const bool active = (tid < Q);

    // ---- Front work: independent of T ----
    u64 cA[4], sA[4], cB[4], sB[4];
    {
        const float4 z4 = make_float4(0.f, 0.f, 0.f, 0.f);
        const float4 x0 = (active && (!GUARD || tid < B))         ? x4[tid]         : z4;
        const float4 x1 = (active && (!GUARD || tid + Q < B))     ? x4[tid + Q]     : z4;
        const float4 x2 = (active && (!GUARD || tid + 2 * Q < B)) ? x4[tid + 2 * Q] : z4;
        const float4 x3 = (active && (!GUARD || tid + 3 * Q < B)) ? x4[tid + 3 * Q] : z4;
        const float* p0 = &x0.x; const float* p1 = &x1.x;
        const float* p2 = &x2.x; const float* p3 = &x3.x;
#pragma unroll
        for (int q = 0; q < 4; q++) {
            float s0, c0, s1, c1, s2, c2, s3, c3;
            __sincosf(p0[q], &s0, &c0);
            __sincosf(p1[q], &s1, &c1);
            __sincosf(p2[q], &s2, &c2);
            __sincosf(p3[q], &s3, &c3);
            cA[q] = pk2(c0, c1); sA[q] = pk2(s0, s1);
            cB[q] = pk2(c2, c3); sB[q] = pk2(s2, s3);
        }
    }

    // ---- Wait for the precompute grid, then stage T in shared ----
    cudaGridDependencySynchronize();
    for (int i = threadIdx.x; i < 4 * 27 * 4; i += blockDim.x) sT[i] = g_Tp[i];
    __syncthreads();

    if (!active) return;

#pragma unroll
    for (int h = 0; h < 2; h++) {           // output halves: w = 2h, 2h+1
        u64 outA[2], outB[2];
#pragma unroll
        for (int wi = 0; wi < 2; wi++) {
            const u64* Tw = &sT[(2 * h + wi) * 27 * 4];
            u64 r0A, r0B;
#pragma unroll
            for (int t0 = 0; t0 < 3; t0++) {
                u64 r1A, r1B;
#pragma unroll
                for (int t1 = 0; t1 < 3; t1++) {
                    u64 r2A, r2B;
#pragma unroll
                    for (int t2 = 0; t2 < 3; t2++) {
                        const int base = ((t0 * 3 + t1) * 3 + t2) * 4;
                        const ulonglong2 ta = *reinterpret_cast<const ulonglong2*>(&Tw[base]);
                        const u64 T2 = Tw[base + 2];
                        const u64 vA = fma2(sA[3], T2, fma2(cA[3], ta.y, ta.x));
                        const u64 vB = fma2(sB[3], T2, fma2(cB[3], ta.y, ta.x));
                        if (t2 == 0)      { r2A = vA;                   r2B = vB; }
                        else if (t2 == 1) { r2A = fma2(cA[2], vA, r2A); r2B = fma2(cB[2], vB, r2B); }
                        else              { r2A = fma2(sA[2], vA, r2A); r2B = fma2(sB[2], vB, r2B); }
                    }
                    if (t1 == 0)      { r1A = r2A;                   r1B = r2B; }
                    else if (t1 == 1) { r1A = fma2(cA[1], r2A, r1A); r1B = fma2(cB[1], r2B, r1B); }
                    else              { r1A = fma2(sA[1], r2A, r1A); r1B = fma2(sB[1], r2B, r1B); }
                }
                if (t0 == 0)      { r0A = r1A;                   r0B = r1B; }
                else if (t0 == 1) { r0A = fma2(cA[0], r1A, r0A); r0B = fma2(cB[0], r1B, r0B); }
                else              { r0A = fma2(sA[0], r1A, r0A); r0B = fma2(sB[0], r1B, r0B); }
            }
            outA[wi] = r0A; outB[wi] = r0B;
        }
        // Store this half: out[e*2 + h] as float2 = (w=2h, w=2h+1)
        float a0l, a0h, a1l, a1h, b0l, b0h, b1l, b1h;
        upk2(outA[0], a0l, a0h); upk2(outA[1], a1l, a1h);
        upk2(outB[0], b0l, b0h); upk2(outB[1], b1l, b1h);
        if (!GUARD || tid < B)         out2[(tid)         * 2 + h] = make_float2(a0l, a1l);
        if (!GUARD || tid + Q < B)     out2[(tid + Q)     * 2 + h] = make_float2(a0h, a1h);
        if (!GUARD || tid + 2 * Q < B) out2[(tid + 2 * Q) * 2 + h] = make_float2(b0l, b1l);
        if (!GUARD || tid + 3 * Q < B) out2[(tid + 3 * Q) * 2 + h] = make_float2(b0h, b1h);
    }
}

extern "C" void kernel_launch(void* const* d_in, const int* in_sizes, int n_in,
                              void* d_out, int out_size) {
    const float* x = (const float*)d_in[0];
    const float* weights = (const float*)d_in[1];
    const int B = in_sizes[0] / 4;            // (B, 4) float32
    const int n_layers = in_sizes[1] / 12;    // (L, 4, 3) float32

    precompute_T<<<1, 256>>>(weights, n_layers);

    const int Q = (B + 3) / 4;                // threads (4 elements each)
    const int blocks = (Q + 255) / 256;

    cudaLaunchConfig_t cfg = {};
    cfg.gridDim = dim3((unsigned)blocks, 1, 1);
    cfg.blockDim = dim3(256, 1, 1);
    cfg.dynamicSmemBytes = 0;
    cfg.stream = 0;
    cudaLaunchAttribute attrs[1];
    attrs[0].id = cudaLaunchAttributeProgrammaticStreamSerialization;
    attrs[0].val.programmaticStreamSerializationAllowed = 1;
    cfg.attrs = attrs;
    cfg.numAttrs = 1;

    if (4 * Q == B) {
        cudaLaunchKernelEx(&cfg, qlayer_main<false>,
                           (const float4*)x, (float2*)d_out, B, Q);
    } else {
        cudaLaunchKernelEx(&cfg, qlayer_main<true>,
                           (const float4*)x, (float2*)d_out, B, Q);
    }
}